// round 2
// baseline (speedup 1.0000x reference)
#include <cuda_runtime.h>
#include <math.h>
#include <stdint.h>

// ---------------------------------------------------------------------------
// SelectiveSSM: x(8,4096,1024) -> out(8,4096,1024), fp32
// Pipeline: prep(weights) ; conv ; GEMM1 (xc @ W_eff^T -> proj[.,192]) ;
//           elementwise (softplus/A_bar/B_bar, transpose to [b][s][t]) ;
//           warp-scan recurrence (+ multiply by C -> y[b][s][t]) ;
//           GEMM2 (y^T-layout @ W_out^T -> out)
// ---------------------------------------------------------------------------

#define DM   1024
#define DS   64
#define LSEQ 4096
#define BATCH 8
#define NPROJ 192                 // delta(64) | B(64) | C(64) after pair-mean fold
#define MTOT (BATCH*LSEQ)         // 32768
#define EPS_SSM 1e-4f

// scratch (static device globals: allocation-free per harness rules)
__device__ float g_xc  [(size_t)MTOT*DM];        // 134 MB
__device__ float g_proj[(size_t)MTOT*NPROJ];     // 25 MB
__device__ float g_Abar[(size_t)BATCH*DS*LSEQ];  // 8.4 MB
__device__ float g_Bbar[(size_t)BATCH*DS*LSEQ];
__device__ float g_Cv  [(size_t)BATCH*DS*LSEQ];
__device__ float g_y   [(size_t)BATCH*DS*LSEQ];
__device__ float g_Wt1 [DM*NPROJ];               // [k][n]  effective in-proj, K-major
__device__ float g_Wt2 [DS*DM];                  // [k][n]  out-proj transposed
__device__ float g_beff[NPROJ];

// ---------------------------------------------------------------------------
// prep: fold pair-means into in_proj weights; transpose both weight mats
// ---------------------------------------------------------------------------
__global__ void prep_kernel(const float* __restrict__ in_w,
                            const float* __restrict__ in_b,
                            const float* __restrict__ out_w)
{
    int stride = gridDim.x * blockDim.x;
    int tid = blockIdx.x * blockDim.x + threadIdx.x;

    // g_Wt1[k][n], n in [0,192)
    for (int i = tid; i < DM * NPROJ; i += stride) {
        int k = i / NPROJ, n = i % NPROJ;
        float v;
        if (n < 64) {
            v = in_w[(size_t)n * DM + k];
        } else if (n < 128) {
            int s = n - 64;
            v = 0.5f * (in_w[(size_t)(64 + 2*s) * DM + k] +
                        in_w[(size_t)(64 + 2*s + 1) * DM + k]);
        } else {
            int s = n - 128;
            v = 0.5f * (in_w[(size_t)(192 + 2*s) * DM + k] +
                        in_w[(size_t)(192 + 2*s + 1) * DM + k]);
        }
        g_Wt1[i] = v;
    }
    // effective bias
    for (int n = tid; n < NPROJ; n += stride) {
        float v;
        if (n < 64) v = in_b[n];
        else if (n < 128) { int s = n - 64;  v = 0.5f * (in_b[64 + 2*s]  + in_b[64 + 2*s + 1]); }
        else              { int s = n - 128; v = 0.5f * (in_b[192 + 2*s] + in_b[192 + 2*s + 1]); }
        g_beff[n] = v;
    }
    // g_Wt2[k][n] = out_w[n][k]
    for (int i = tid; i < DS * DM; i += stride) {
        int k = i / DM, n = i % DM;
        g_Wt2[i] = out_w[(size_t)n * DS + k];
    }
}

// ---------------------------------------------------------------------------
// depthwise conv, width 4, pad 1; output row t==L-1 forced to exact 0
// (matches reference: conv gives L-1 rows, then zero-pad, bias added pre-pad)
// ---------------------------------------------------------------------------
__global__ void conv_kernel(const float* __restrict__ x,
                            const float* __restrict__ conv_w,
                            const float* __restrict__ conv_b)
{
    size_t idx = (size_t)blockIdx.x * blockDim.x + threadIdx.x;
    if (idx >= (size_t)MTOT * DM) return;
    int d = (int)(idx % DM);
    size_t bt = idx / DM;
    int t = (int)(bt % LSEQ);
    size_t b = bt / LSEQ;
    if (t == LSEQ - 1) { g_xc[idx] = 0.0f; return; }
    const float* xb = x + b * (size_t)LSEQ * DM;
    float w0 = conv_w[d*4+0], w1 = conv_w[d*4+1], w2 = conv_w[d*4+2], w3 = conv_w[d*4+3];
    float r = conv_b[d];
    int tm1 = t - 1;
    if (tm1 >= 0)       r += w0 * xb[(size_t)tm1 * DM + d];
    r += w1 * xb[(size_t)t * DM + d];
    r += w2 * xb[(size_t)(t+1) * DM + d];
    if (t + 2 < LSEQ)   r += w3 * xb[(size_t)(t+2) * DM + d];
    g_xc[idx] = r;
}

// ---------------------------------------------------------------------------
// GEMM1: proj[M=32768, N=192] = xc[M,1024] @ g_Wt1[1024,192] + beff
// BM=128, BN=64, BK=16, 256 thr, per-thread 8x4, double-buffered smem
// ---------------------------------------------------------------------------
__global__ __launch_bounds__(256) void gemm1_kernel()
{
    __shared__ float As[2][16][132];   // [k][m], padded
    __shared__ float Bs[2][16][64];    // [k][n]

    const int tid = threadIdx.x;
    const int m0 = blockIdx.x * 128;
    const int n0 = blockIdx.y * 64;
    const int tx = tid & 15, ty = tid >> 4;
    const int a_row = tid >> 2;            // 0..63 (two rows: a_row, a_row+64)
    const int a_c4  = (tid & 3) * 4;       // k sub-col
    const int b_row = tid >> 4;            // 0..15
    const int b_c4  = (tid & 15) * 4;      // n sub-col

    float acc[8][4];
#pragma unroll
    for (int i = 0; i < 8; i++)
#pragma unroll
        for (int j = 0; j < 4; j++) acc[i][j] = 0.0f;

    const int NIT = DM / 16;

    // prologue: tile 0
    {
        float4 va0 = *(const float4*)&g_xc[(size_t)(m0 + a_row)      * DM + a_c4];
        float4 va1 = *(const float4*)&g_xc[(size_t)(m0 + a_row + 64) * DM + a_c4];
        float4 vb  = *(const float4*)&g_Wt1[(size_t)b_row * NPROJ + n0 + b_c4];
        As[0][a_c4+0][a_row] = va0.x; As[0][a_c4+1][a_row] = va0.y;
        As[0][a_c4+2][a_row] = va0.z; As[0][a_c4+3][a_row] = va0.w;
        As[0][a_c4+0][a_row+64] = va1.x; As[0][a_c4+1][a_row+64] = va1.y;
        As[0][a_c4+2][a_row+64] = va1.z; As[0][a_c4+3][a_row+64] = va1.w;
        *(float4*)&Bs[0][b_row][b_c4] = vb;
    }
    __syncthreads();

    for (int it = 0; it < NIT; ++it) {
        const int cur = it & 1, nxt = cur ^ 1;
        float4 va0, va1, vb;
        const bool hasNext = (it + 1 < NIT);
        if (hasNext) {
            int k0 = (it + 1) * 16;
            va0 = *(const float4*)&g_xc[(size_t)(m0 + a_row)      * DM + k0 + a_c4];
            va1 = *(const float4*)&g_xc[(size_t)(m0 + a_row + 64) * DM + k0 + a_c4];
            vb  = *(const float4*)&g_Wt1[(size_t)(k0 + b_row) * NPROJ + n0 + b_c4];
        }
#pragma unroll
        for (int k = 0; k < 16; ++k) {
            float4 a0 = *(const float4*)&As[cur][k][ty*8];
            float4 a1 = *(const float4*)&As[cur][k][ty*8+4];
            float4 b  = *(const float4*)&Bs[cur][k][tx*4];
            float av[8] = {a0.x,a0.y,a0.z,a0.w,a1.x,a1.y,a1.z,a1.w};
            float bv[4] = {b.x,b.y,b.z,b.w};
#pragma unroll
            for (int i = 0; i < 8; i++)
#pragma unroll
                for (int j = 0; j < 4; j++)
                    acc[i][j] = fmaf(av[i], bv[j], acc[i][j]);
        }
        if (hasNext) {
            As[nxt][a_c4+0][a_row] = va0.x; As[nxt][a_c4+1][a_row] = va0.y;
            As[nxt][a_c4+2][a_row] = va0.z; As[nxt][a_c4+3][a_row] = va0.w;
            As[nxt][a_c4+0][a_row+64] = va1.x; As[nxt][a_c4+1][a_row+64] = va1.y;
            As[nxt][a_c4+2][a_row+64] = va1.z; As[nxt][a_c4+3][a_row+64] = va1.w;
            *(float4*)&Bs[nxt][b_row][b_c4] = vb;
        }
        __syncthreads();
    }

#pragma unroll
    for (int i = 0; i < 8; i++) {
        int row = m0 + ty * 8 + i;
#pragma unroll
        for (int j = 0; j < 4; j++) {
            int col = n0 + tx * 4 + j;
            g_proj[(size_t)row * NPROJ + col] = acc[i][j] + g_beff[col];
        }
    }
}

// ---------------------------------------------------------------------------
// elementwise: proj -> A_bar, B_bar, C in [b][s][t] layout (smem transpose)
// block = 256 threads handles 32 consecutive rows (one b, t-chunk of 32)
// ---------------------------------------------------------------------------
__global__ __launch_bounds__(256) void elem_kernel(const float* __restrict__ A_log)
{
    __shared__ float sp[32][NPROJ + 1];
    __shared__ float sA[DS];
    const int tid = threadIdx.x;
    const int m0 = blockIdx.x * 32;

    for (int i = tid; i < 32 * NPROJ; i += 256)
        sp[i / NPROJ][i % NPROJ] = g_proj[(size_t)m0 * NPROJ + i];
    if (tid < DS) sA[tid] = -expf(A_log[tid]);
    __syncthreads();

    const int t  = tid & 31;
    const int sr = tid >> 5;          // 0..7
    const int bidx  = m0 / LSEQ;
    const int tbase = m0 % LSEQ;

#pragma unroll
    for (int i = 0; i < 8; ++i) {
        int s = sr * 8 + i;
        float draw = sp[t][s];
        float bin  = sp[t][64 + s];
        float cc   = sp[t][128 + s];
        float A    = sA[s];
        float delta = (draw > 20.0f) ? draw : log1pf(expf(draw));
        float dA   = delta * A;
        float abar = expf(dA);
        float scale;
        if (fabsf(A) < EPS_SSM)
            scale = 1.0f + dA * 0.5f + dA * dA * (1.0f / 6.0f);
        else
            scale = (abar - 1.0f) / A;
        size_t o = ((size_t)bidx * DS + s) * LSEQ + tbase + t;
        g_Abar[o] = abar;
        g_Bbar[o] = scale * bin;
        g_Cv[o]   = cc;
    }
}

// ---------------------------------------------------------------------------
// recurrence: one warp per (b,s) sequence; Hillis-Steele affine warp scan
// y[b][s][t] = C * h
// ---------------------------------------------------------------------------
__global__ __launch_bounds__(128) void scan_kernel()
{
    const int warp = (blockIdx.x * blockDim.x + threadIdx.x) >> 5;
    const int lane = threadIdx.x & 31;
    if (warp >= BATCH * DS) return;
    const size_t base = (size_t)warp * LSEQ;
    const float* ap = g_Abar + base;
    const float* bp = g_Bbar + base;
    const float* cp = g_Cv   + base;
    float*       yp = g_y    + base;

    float carry = 0.0f;   // h at t0-1
    for (int t0 = 0; t0 < LSEQ; t0 += 32) {
        float a = ap[t0 + lane];
        float b = bp[t0 + lane];
#pragma unroll
        for (int off = 1; off < 32; off <<= 1) {
            float apv = __shfl_up_sync(0xffffffffu, a, off);
            float bpv = __shfl_up_sync(0xffffffffu, b, off);
            if (lane >= off) { b = fmaf(a, bpv, b); a *= apv; }
        }
        float h = fmaf(a, carry, b);
        yp[t0 + lane] = cp[t0 + lane] * h;
        carry = __shfl_sync(0xffffffffu, h, 31);
    }
}

// ---------------------------------------------------------------------------
// GEMM2: out[M=32768, N=1024] = y(K-major [b][k][t]) @ g_Wt2[64,1024] + out_b
// BM=128, BN=128, BK=16, 256 thr, per-thread 8x8, double-buffered smem
// ---------------------------------------------------------------------------
__global__ __launch_bounds__(256) void gemm2_kernel(const float* __restrict__ out_b,
                                                    float* __restrict__ out)
{
    __shared__ float As[2][16][128];   // [k][m]
    __shared__ float Bs[2][16][128];   // [k][n]

    const int tid = threadIdx.x;
    const int m0 = blockIdx.x * 128;
    const int n0 = blockIdx.y * 128;
    const int bb = m0 >> 12;               // m0 / 4096
    const int t0 = m0 & (LSEQ - 1);
    const int tx = tid & 15, ty = tid >> 4;
    const int kr = tid >> 5;               // 0..7 (handles kr and kr+8)
    const int cg = (tid & 31) * 4;

    const float* ybase = g_y + (size_t)bb * DS * LSEQ;

    float acc[8][8];
#pragma unroll
    for (int i = 0; i < 8; i++)
#pragma unroll
        for (int j = 0; j < 8; j++) acc[i][j] = 0.0f;

    const int NIT = DS / 16;   // 4

    {
        float4 va0 = *(const float4*)&ybase[(size_t)kr       * LSEQ + t0 + cg];
        float4 va1 = *(const float4*)&ybase[(size_t)(kr + 8) * LSEQ + t0 + cg];
        float4 vb0 = *(const float4*)&g_Wt2[(size_t)kr       * DM + n0 + cg];
        float4 vb1 = *(const float4*)&g_Wt2[(size_t)(kr + 8) * DM + n0 + cg];
        *(float4*)&As[0][kr][cg]     = va0;
        *(float4*)&As[0][kr + 8][cg] = va1;
        *(float4*)&Bs[0][kr][cg]     = vb0;
        *(float4*)&Bs[0][kr + 8][cg] = vb1;
    }
    __syncthreads();

    for (int it = 0; it < NIT; ++it) {
        const int cur = it & 1, nxt = cur ^ 1;
        float4 va0, va1, vb0, vb1;
        const bool hasNext = (it + 1 < NIT);
        if (hasNext) {
            int k0 = (it + 1) * 16;
            va0 = *(const float4*)&ybase[(size_t)(k0 + kr)     * LSEQ + t0 + cg];
            va1 = *(const float4*)&ybase[(size_t)(k0 + kr + 8) * LSEQ + t0 + cg];
            vb0 = *(const float4*)&g_Wt2[(size_t)(k0 + kr)     * DM + n0 + cg];
            vb1 = *(const float4*)&g_Wt2[(size_t)(k0 + kr + 8) * DM + n0 + cg];
        }
#pragma unroll
        for (int k = 0; k < 16; ++k) {
            float4 a0 = *(const float4*)&As[cur][k][ty*8];
            float4 a1 = *(const float4*)&As[cur][k][ty*8+4];
            float4 b0 = *(const float4*)&Bs[cur][k][tx*8];
            float4 b1 = *(const float4*)&Bs[cur][k][tx*8+4];
            float av[8] = {a0.x,a0.y,a0.z,a0.w,a1.x,a1.y,a1.z,a1.w};
            float bv[8] = {b0.x,b0.y,b0.z,b0.w,b1.x,b1.y,b1.z,b1.w};
#pragma unroll
            for (int i = 0; i < 8; i++)
#pragma unroll
                for (int j = 0; j < 8; j++)
                    acc[i][j] = fmaf(av[i], bv[j], acc[i][j]);
        }
        if (hasNext) {
            *(float4*)&As[nxt][kr][cg]     = va0;
            *(float4*)&As[nxt][kr + 8][cg] = va1;
            *(float4*)&Bs[nxt][kr][cg]     = vb0;
            *(float4*)&Bs[nxt][kr + 8][cg] = vb1;
        }
        __syncthreads();
    }

#pragma unroll
    for (int i = 0; i < 8; i++) {
        size_t row = (size_t)(m0 + ty * 8 + i);
#pragma unroll
        for (int j = 0; j < 8; j++) {
            int col = n0 + tx * 8 + j;
            out[row * DM + col] = acc[i][j] + out_b[col];
        }
    }
}

// ---------------------------------------------------------------------------
extern "C" void kernel_launch(void* const* d_in, const int* in_sizes, int n_in,
                              void* d_out, int out_size)
{
    const float* x      = (const float*)d_in[0];
    const float* conv_w = (const float*)d_in[1];
    const float* conv_b = (const float*)d_in[2];
    const float* in_w   = (const float*)d_in[3];
    const float* in_b   = (const float*)d_in[4];
    const float* A_log  = (const float*)d_in[5];
    const float* out_w  = (const float*)d_in[6];
    const float* out_b  = (const float*)d_in[7];
    float* out = (float*)d_out;

    prep_kernel<<<256, 256>>>(in_w, in_b, out_w);

    {
        size_t total = (size_t)MTOT * DM;
        int threads = 256;
        int blocks = (int)((total + threads - 1) / threads);
        conv_kernel<<<blocks, threads>>>(x, conv_w, conv_b);
    }

    {
        dim3 grid(MTOT / 128, NPROJ / 64);
        gemm1_kernel<<<grid, 256>>>();
    }

    elem_kernel<<<MTOT / 32, 256>>>(A_log);

    scan_kernel<<<(BATCH * DS * 32) / 128, 128>>>();

    {
        dim3 grid(MTOT / 128, DM / 128);
        gemm2_kernel<<<grid, 256>>>(out_b, out);
    }
}

// round 4
// speedup vs baseline: 1.4749x; 1.4749x over previous
#include <cuda_runtime.h>
#include <cuda_bf16.h>
#include <math.h>
#include <stdint.h>

// ---------------------------------------------------------------------------
// SelectiveSSM via mma.sync bf16 (hi/lo split, 3-product fp32 emulation)
//  prep  : fold pair-means into W1eff, split W1/W2 into bf16 hi/lo
//  conv  : depthwise conv -> xc bf16 hi/lo [m][k]
//  gemm1 : HMMA  proj[32768,192] = xc @ W1eff^T (+bias)
//  elem  : softplus/exp/scale -> Abar/Bbar/C in [b][s][t]
//  scan  : warp-scan recurrence -> y[b][s][t]
//  gemm2 : HMMA  out[32768,1024] = y^T @ W2^T + bias
// ---------------------------------------------------------------------------

#define DM    1024
#define DS    64
#define LSEQ  4096
#define BATCH 8
#define NPROJ 192
#define MTOT  (BATCH*LSEQ)
#define EPS_SSM 1e-4f

// ------------------------------- scratch -----------------------------------
__device__ __nv_bfloat16 g_xchi[(size_t)MTOT*DM];
__device__ __nv_bfloat16 g_xclo[(size_t)MTOT*DM];
__device__ __nv_bfloat16 g_W1hi[NPROJ*DM];
__device__ __nv_bfloat16 g_W1lo[NPROJ*DM];
__device__ __nv_bfloat16 g_W2hi[DM*DS];
__device__ __nv_bfloat16 g_W2lo[DM*DS];
__device__ float g_proj[(size_t)MTOT*NPROJ];
__device__ float g_beff[NPROJ];
__device__ float g_negA[DS];
__device__ float g_Abar[(size_t)BATCH*DS*LSEQ];
__device__ float g_Bbar[(size_t)BATCH*DS*LSEQ];
__device__ float g_Cv  [(size_t)BATCH*DS*LSEQ];
__device__ float g_y   [(size_t)BATCH*DS*LSEQ];

// ------------------------------ helpers ------------------------------------
__device__ __forceinline__ uint32_t smem_u32(const void* p) {
    uint32_t a;
    asm("{ .reg .u64 t; cvta.to.shared.u64 t, %1; cvt.u32.u64 %0, t; }"
        : "=r"(a) : "l"(p));
    return a;
}
__device__ __forceinline__ void cp16(uint32_t dst, const void* src) {
    asm volatile("cp.async.ca.shared.global [%0], [%1], 16;"
                 :: "r"(dst), "l"(src));
}
#define CP_COMMIT()  asm volatile("cp.async.commit_group;" ::: "memory")
#define CP_WAIT0()   asm volatile("cp.async.wait_group 0;" ::: "memory")
#define CP_WAIT1()   asm volatile("cp.async.wait_group 1;" ::: "memory")

__device__ __forceinline__ void mma_bf16(float& c0, float& c1, float& c2, float& c3,
                                         uint32_t a0, uint32_t a1, uint32_t a2, uint32_t a3,
                                         uint32_t b0, uint32_t b1) {
    asm volatile("mma.sync.aligned.m16n8k16.row.col.f32.bf16.bf16.f32 "
                 "{%0,%1,%2,%3}, {%4,%5,%6,%7}, {%8,%9}, {%0,%1,%2,%3};"
                 : "+f"(c0), "+f"(c1), "+f"(c2), "+f"(c3)
                 : "r"(a0), "r"(a1), "r"(a2), "r"(a3), "r"(b0), "r"(b1));
}

__device__ __forceinline__ void split_bf16(float x, __nv_bfloat16& hi, __nv_bfloat16& lo) {
    hi = __float2bfloat16(x);
    lo = __float2bfloat16(x - __bfloat162float(hi));
}

// ---------------------------------------------------------------------------
// prep
// ---------------------------------------------------------------------------
__global__ void prep_kernel(const float* __restrict__ in_w,
                            const float* __restrict__ in_b,
                            const float* __restrict__ out_w,
                            const float* __restrict__ A_log)
{
    int stride = gridDim.x * blockDim.x;
    int tid = blockIdx.x * blockDim.x + threadIdx.x;

    for (int i = tid; i < NPROJ * DM; i += stride) {
        int n = i / DM, k = i % DM;
        float v;
        if (n < 64) {
            v = in_w[(size_t)n * DM + k];
        } else if (n < 128) {
            int s = n - 64;
            v = 0.5f * (in_w[(size_t)(64 + 2*s) * DM + k] +
                        in_w[(size_t)(64 + 2*s + 1) * DM + k]);
        } else {
            int s = n - 128;
            v = 0.5f * (in_w[(size_t)(192 + 2*s) * DM + k] +
                        in_w[(size_t)(192 + 2*s + 1) * DM + k]);
        }
        __nv_bfloat16 hi, lo; split_bf16(v, hi, lo);
        g_W1hi[i] = hi; g_W1lo[i] = lo;
    }
    for (int i = tid; i < DM * DS; i += stride) {
        __nv_bfloat16 hi, lo; split_bf16(out_w[i], hi, lo);
        g_W2hi[i] = hi; g_W2lo[i] = lo;
    }
    for (int n = tid; n < NPROJ; n += stride) {
        float v;
        if (n < 64) v = in_b[n];
        else if (n < 128) { int s = n - 64;  v = 0.5f * (in_b[64 + 2*s]  + in_b[64 + 2*s + 1]); }
        else              { int s = n - 128; v = 0.5f * (in_b[192 + 2*s] + in_b[192 + 2*s + 1]); }
        g_beff[n] = v;
    }
    for (int s = tid; s < DS; s += stride) g_negA[s] = -expf(A_log[s]);
}

// ---------------------------------------------------------------------------
// conv
// ---------------------------------------------------------------------------
__global__ void conv_kernel(const float* __restrict__ x,
                            const float* __restrict__ conv_w,
                            const float* __restrict__ conv_b)
{
    size_t idx = (size_t)blockIdx.x * blockDim.x + threadIdx.x;
    if (idx >= (size_t)MTOT * DM) return;
    int d = (int)(idx % DM);
    size_t bt = idx / DM;
    int t = (int)(bt % LSEQ);
    size_t b = bt / LSEQ;
    float r;
    if (t == LSEQ - 1) {
        r = 0.0f;
    } else {
        const float* xb = x + b * (size_t)LSEQ * DM;
        float w0 = conv_w[d*4+0], w1 = conv_w[d*4+1], w2 = conv_w[d*4+2], w3 = conv_w[d*4+3];
        r = conv_b[d];
        if (t - 1 >= 0)   r += w0 * xb[(size_t)(t-1) * DM + d];
        r += w1 * xb[(size_t)t * DM + d];
        r += w2 * xb[(size_t)(t+1) * DM + d];
        if (t + 2 < LSEQ) r += w3 * xb[(size_t)(t+2) * DM + d];
    }
    __nv_bfloat16 hi, lo; split_bf16(r, hi, lo);
    g_xchi[idx] = hi; g_xclo[idx] = lo;
}

// ---------------------------------------------------------------------------
// GEMM1: proj = xc @ W1eff^T + beff
// BM=128, BN=64, BK=64, 256 thr (8 warps = 2m x 4n), warp tile 64x16
// smem per stage: Ahi(128x144B) Alo Bhi(64x144B) Blo ; double buffered
// ---------------------------------------------------------------------------
#define G1_ROWB   144                 // 64 bf16 * 2 + 16B pad
#define G1_A_SZ   (128 * G1_ROWB)     // 18432
#define G1_B_SZ   (64 * G1_ROWB)      // 9216
#define G1_STAGE  (2*G1_A_SZ + 2*G1_B_SZ)   // 55296
#define G1_SMEM   (2 * G1_STAGE)            // 110592

__global__ __launch_bounds__(256, 2) void gemm1_kernel()
{
    extern __shared__ char smem[];
    const uint32_t sb = smem_u32(smem);
    const int tid  = threadIdx.x;
    const int wid  = tid >> 5, lane = tid & 31;
    const int wm   = wid & 1;           // 0..1 -> m offset 64*wm
    const int wn   = wid >> 1;          // 0..3 -> n offset 16*wn
    const int m0   = blockIdx.x * 128;
    const int n0   = blockIdx.y * 64;

    const int lr  = lane >> 2;          // 0..7
    const int lc  = lane & 3;           // 0..3

    float acc[4][2][4];
#pragma unroll
    for (int i = 0; i < 4; i++)
#pragma unroll
        for (int j = 0; j < 2; j++)
#pragma unroll
            for (int e = 0; e < 4; e++) acc[i][j][e] = 0.0f;

    // stage loader via cp.async
    auto load_stage = [&](int k0, int stage) {
        uint32_t base = sb + stage * G1_STAGE;
        uint32_t Ahi = base, Alo = base + G1_A_SZ;
        uint32_t Bhi = base + 2*G1_A_SZ, Blo = Bhi + G1_B_SZ;
#pragma unroll
        for (int i = 0; i < 4; ++i) {               // A: 1024 x 16B
            int idx = tid + i * 256;
            int row = idx >> 3, cq = idx & 7;
            size_t g = (size_t)(m0 + row) * DM + k0 + cq * 8;
            uint32_t d = row * G1_ROWB + cq * 16;
            cp16(Ahi + d, &g_xchi[g]);
            cp16(Alo + d, &g_xclo[g]);
        }
#pragma unroll
        for (int i = 0; i < 2; ++i) {               // B: 512 x 16B
            int idx = tid + i * 256;
            int row = idx >> 3, cq = idx & 7;
            size_t g = (size_t)(n0 + row) * DM + k0 + cq * 8;
            uint32_t d = row * G1_ROWB + cq * 16;
            cp16(Bhi + d, &g_W1hi[g]);
            cp16(Blo + d, &g_W1lo[g]);
        }
    };

    load_stage(0, 0);
    CP_COMMIT();

    const int NCH = DM / 64;   // 16
    for (int c = 0; c < NCH; ++c) {
        if (c + 1 < NCH) { load_stage((c + 1) * 64, (c + 1) & 1); CP_COMMIT(); CP_WAIT1(); }
        else             { CP_WAIT0(); }
        __syncthreads();

        const char* base = smem + (c & 1) * G1_STAGE;
        const char* Ahi = base;
        const char* Alo = base + G1_A_SZ;
        const char* Bhi = base + 2*G1_A_SZ;
        const char* Blo = Bhi + G1_B_SZ;

#pragma unroll
        for (int ks = 0; ks < 4; ++ks) {
            const int kb = ks * 32 + lc * 4;        // byte offset of k-pair
            uint32_t ah[4][4], al[4][4];
#pragma unroll
            for (int mf = 0; mf < 4; ++mf) {
                int r0 = wm * 64 + mf * 16 + lr;
                const char* p0 = Ahi + r0 * G1_ROWB + kb;
                const char* p1 = Ahi + (r0 + 8) * G1_ROWB + kb;
                ah[mf][0] = *(const uint32_t*)(p0);
                ah[mf][1] = *(const uint32_t*)(p1);
                ah[mf][2] = *(const uint32_t*)(p0 + 16);
                ah[mf][3] = *(const uint32_t*)(p1 + 16);
                const char* q0 = Alo + r0 * G1_ROWB + kb;
                const char* q1 = Alo + (r0 + 8) * G1_ROWB + kb;
                al[mf][0] = *(const uint32_t*)(q0);
                al[mf][1] = *(const uint32_t*)(q1);
                al[mf][2] = *(const uint32_t*)(q0 + 16);
                al[mf][3] = *(const uint32_t*)(q1 + 16);
            }
            uint32_t bh[2][2], bl[2][2];
#pragma unroll
            for (int nf = 0; nf < 2; ++nf) {
                int n = wn * 16 + nf * 8 + lr;
                const char* p = Bhi + n * G1_ROWB + kb;
                bh[nf][0] = *(const uint32_t*)(p);
                bh[nf][1] = *(const uint32_t*)(p + 16);
                const char* q = Blo + n * G1_ROWB + kb;
                bl[nf][0] = *(const uint32_t*)(q);
                bl[nf][1] = *(const uint32_t*)(q + 16);
            }
#pragma unroll
            for (int mf = 0; mf < 4; ++mf)
#pragma unroll
                for (int nf = 0; nf < 2; ++nf) {
                    float* cc = acc[mf][nf];
                    mma_bf16(cc[0], cc[1], cc[2], cc[3],
                             ah[mf][0], ah[mf][1], ah[mf][2], ah[mf][3],
                             bh[nf][0], bh[nf][1]);
                    mma_bf16(cc[0], cc[1], cc[2], cc[3],
                             ah[mf][0], ah[mf][1], ah[mf][2], ah[mf][3],
                             bl[nf][0], bl[nf][1]);
                    mma_bf16(cc[0], cc[1], cc[2], cc[3],
                             al[mf][0], al[mf][1], al[mf][2], al[mf][3],
                             bh[nf][0], bh[nf][1]);
                }
        }
        __syncthreads();
    }

    // epilogue: + bias, float2 stores
#pragma unroll
    for (int mf = 0; mf < 4; ++mf) {
        int row = m0 + wm * 64 + mf * 16 + lr;
#pragma unroll
        for (int nf = 0; nf < 2; ++nf) {
            int col = n0 + wn * 16 + nf * 8 + lc * 2;
            float b0 = __ldg(&g_beff[col]), b1 = __ldg(&g_beff[col + 1]);
            float2 v0 = make_float2(acc[mf][nf][0] + b0, acc[mf][nf][1] + b1);
            float2 v1 = make_float2(acc[mf][nf][2] + b0, acc[mf][nf][3] + b1);
            *(float2*)&g_proj[(size_t)row * NPROJ + col]       = v0;
            *(float2*)&g_proj[(size_t)(row + 8) * NPROJ + col] = v1;
        }
    }
}

// ---------------------------------------------------------------------------
// elem: proj -> Abar/Bbar/C in [b][s][t]
// ---------------------------------------------------------------------------
__global__ __launch_bounds__(256) void elem_kernel()
{
    __shared__ float sp[32][NPROJ + 1];
    __shared__ float sA[DS];
    const int tid = threadIdx.x;
    const int m0 = blockIdx.x * 32;

    for (int i = tid; i < 32 * NPROJ; i += 256)
        sp[i / NPROJ][i % NPROJ] = g_proj[(size_t)m0 * NPROJ + i];
    if (tid < DS) sA[tid] = g_negA[tid];
    __syncthreads();

    const int t  = tid & 31;
    const int sr = tid >> 5;
    const int bidx  = m0 / LSEQ;
    const int tbase = m0 % LSEQ;

#pragma unroll
    for (int i = 0; i < 8; ++i) {
        int s = sr * 8 + i;
        float draw = sp[t][s];
        float bin  = sp[t][64 + s];
        float cc   = sp[t][128 + s];
        float A    = sA[s];
        float delta = (draw > 20.0f) ? draw : log1pf(expf(draw));
        float dA   = delta * A;
        float abar = expf(dA);
        float scale;
        if (fabsf(A) < EPS_SSM)
            scale = 1.0f + dA * 0.5f + dA * dA * (1.0f / 6.0f);
        else
            scale = (abar - 1.0f) / A;
        size_t o = ((size_t)(bidx * DS + s) << 12) + tbase + t;
        g_Abar[o] = abar;
        g_Bbar[o] = scale * bin;
        g_Cv[o]   = cc;
    }
}

// ---------------------------------------------------------------------------
// scan
// ---------------------------------------------------------------------------
__global__ __launch_bounds__(128) void scan_kernel()
{
    const int warp = (blockIdx.x * blockDim.x + threadIdx.x) >> 5;
    const int lane = threadIdx.x & 31;
    if (warp >= BATCH * DS) return;
    const size_t base = (size_t)warp * LSEQ;
    const float* ap = g_Abar + base;
    const float* bp = g_Bbar + base;
    const float* cp = g_Cv   + base;
    float*       yp = g_y    + base;

    float carry = 0.0f;
    for (int t0 = 0; t0 < LSEQ; t0 += 32) {
        float a = ap[t0 + lane];
        float b = bp[t0 + lane];
#pragma unroll
        for (int off = 1; off < 32; off <<= 1) {
            float apv = __shfl_up_sync(0xffffffffu, a, off);
            float bpv = __shfl_up_sync(0xffffffffu, b, off);
            if (lane >= off) { b = fmaf(a, bpv, b); a *= apv; }
        }
        float h = fmaf(a, carry, b);
        yp[t0 + lane] = cp[t0 + lane] * h;
        carry = __shfl_sync(0xffffffffu, h, 31);
    }
}

// ---------------------------------------------------------------------------
// GEMM2: out[m=(b,t)][n] = sum_s y[b][s][t] * W2[n][s] + out_b[n]
// BM=128 (t), BN=128 (n), K=64 single stage; warp tile 64x32
// smem: Ahi[128x144] Alo Bhi[128x144] Blo
// ---------------------------------------------------------------------------
#define G2_ROWB  144
#define G2_T_SZ  (128 * G2_ROWB)   // 18432
#define G2_SMEM  (4 * G2_T_SZ)     // 73728

__global__ __launch_bounds__(256, 2) void gemm2_kernel(const float* __restrict__ out_b,
                                                       float* __restrict__ out)
{
    extern __shared__ char smem[];
    const uint32_t sb = smem_u32(smem);
    const int tid = threadIdx.x;
    const int wid = tid >> 5, lane = tid & 31;
    const int wm  = wid & 1;
    const int wn  = wid >> 1;
    const int m0  = blockIdx.x * 128;
    const int n0  = blockIdx.y * 128;
    const int b   = m0 >> 12;
    const int t0  = m0 & (LSEQ - 1);
    const int lr  = lane >> 2;
    const int lc  = lane & 3;

    char* Ahi = smem;
    char* Alo = smem + G2_T_SZ;
    char* Bhi = smem + 2*G2_T_SZ;
    char* Blo = smem + 3*G2_T_SZ;

    // B via cp.async: W2[n0+n][s] rows of 128B
#pragma unroll
    for (int i = 0; i < 4; ++i) {
        int idx = tid + i * 256;
        int row = idx >> 3, cq = idx & 7;
        size_t g = (size_t)(n0 + row) * DS + cq * 8;
        uint32_t d = row * G2_ROWB + cq * 16;
        cp16(sb + 2*G2_T_SZ + d, &g_W2hi[g]);
        cp16(sb + 3*G2_T_SZ + d, &g_W2lo[g]);
    }
    CP_COMMIT();

    // A: transpose y[b][s][t0..t0+127] -> As[t][s], split bf16
    {
        const float* yb = g_y + ((size_t)b * DS << 12);
        for (int idx = tid; idx < DS * 32; idx += 256) {
            int s = idx >> 5, tq = idx & 31;
            float4 v = *(const float4*)&yb[((size_t)s << 12) + t0 + tq * 4];
            float vv[4] = {v.x, v.y, v.z, v.w};
#pragma unroll
            for (int e = 0; e < 4; ++e) {
                int t = tq * 4 + e;
                __nv_bfloat16 hi, lo; split_bf16(vv[e], hi, lo);
                *(__nv_bfloat16*)(Ahi + t * G2_ROWB + s * 2) = hi;
                *(__nv_bfloat16*)(Alo + t * G2_ROWB + s * 2) = lo;
            }
        }
    }
    CP_WAIT0();
    __syncthreads();

    float acc[4][4][4];
#pragma unroll
    for (int i = 0; i < 4; i++)
#pragma unroll
        for (int j = 0; j < 4; j++)
#pragma unroll
            for (int e = 0; e < 4; e++) acc[i][j][e] = 0.0f;

#pragma unroll
    for (int ks = 0; ks < 4; ++ks) {
        const int kb = ks * 32 + lc * 4;
        uint32_t ah[4][4], al[4][4];
#pragma unroll
        for (int mf = 0; mf < 4; ++mf) {
            int r0 = wm * 64 + mf * 16 + lr;
            const char* p0 = Ahi + r0 * G2_ROWB + kb;
            const char* p1 = Ahi + (r0 + 8) * G2_ROWB + kb;
            ah[mf][0] = *(const uint32_t*)(p0);
            ah[mf][1] = *(const uint32_t*)(p1);
            ah[mf][2] = *(const uint32_t*)(p0 + 16);
            ah[mf][3] = *(const uint32_t*)(p1 + 16);
            const char* q0 = Alo + r0 * G2_ROWB + kb;
            const char* q1 = Alo + (r0 + 8) * G2_ROWB + kb;
            al[mf][0] = *(const uint32_t*)(q0);
            al[mf][1] = *(const uint32_t*)(q1);
            al[mf][2] = *(const uint32_t*)(q0 + 16);
            al[mf][3] = *(const uint32_t*)(q1 + 16);
        }
        uint32_t bh[4][2], bl[4][2];
#pragma unroll
        for (int nf = 0; nf < 4; ++nf) {
            int n = wn * 32 + nf * 8 + lr;
            const char* p = Bhi + n * G2_ROWB + kb;
            bh[nf][0] = *(const uint32_t*)(p);
            bh[nf][1] = *(const uint32_t*)(p + 16);
            const char* q = Blo + n * G2_ROWB + kb;
            bl[nf][0] = *(const uint32_t*)(q);
            bl[nf][1] = *(const uint32_t*)(q + 16);
        }
#pragma unroll
        for (int mf = 0; mf < 4; ++mf)
#pragma unroll
            for (int nf = 0; nf < 4; ++nf) {
                float* cc = acc[mf][nf];
                mma_bf16(cc[0], cc[1], cc[2], cc[3],
                         ah[mf][0], ah[mf][1], ah[mf][2], ah[mf][3],
                         bh[nf][0], bh[nf][1]);
                mma_bf16(cc[0], cc[1], cc[2], cc[3],
                         ah[mf][0], ah[mf][1], ah[mf][2], ah[mf][3],
                         bl[nf][0], bl[nf][1]);
                mma_bf16(cc[0], cc[1], cc[2], cc[3],
                         al[mf][0], al[mf][1], al[mf][2], al[mf][3],
                         bh[nf][0], bh[nf][1]);
            }
    }

    // epilogue: +bias, float2 stores (32B-sector aligned per lane quad)
#pragma unroll
    for (int mf = 0; mf < 4; ++mf) {
        int row = m0 + wm * 64 + mf * 16 + lr;
#pragma unroll
        for (int nf = 0; nf < 4; ++nf) {
            int col = n0 + wn * 32 + nf * 8 + lc * 2;
            float b0 = __ldg(&out_b[col]), b1 = __ldg(&out_b[col + 1]);
            float2 v0 = make_float2(acc[mf][nf][0] + b0, acc[mf][nf][1] + b1);
            float2 v1 = make_float2(acc[mf][nf][2] + b0, acc[mf][nf][3] + b1);
            *(float2*)&out[(size_t)row * DM + col]       = v0;
            *(float2*)&out[(size_t)(row + 8) * DM + col] = v1;
        }
    }
}

// ---------------------------------------------------------------------------
extern "C" void kernel_launch(void* const* d_in, const int* in_sizes, int n_in,
                              void* d_out, int out_size)
{
    const float* x      = (const float*)d_in[0];
    const float* conv_w = (const float*)d_in[1];
    const float* conv_b = (const float*)d_in[2];
    const float* in_w   = (const float*)d_in[3];
    const float* in_b   = (const float*)d_in[4];
    const float* A_log  = (const float*)d_in[5];
    const float* out_w  = (const float*)d_in[6];
    const float* out_b  = (const float*)d_in[7];
    float* out = (float*)d_out;

    cudaFuncSetAttribute(gemm1_kernel, cudaFuncAttributeMaxDynamicSharedMemorySize, G1_SMEM);
    cudaFuncSetAttribute(gemm2_kernel, cudaFuncAttributeMaxDynamicSharedMemorySize, G2_SMEM);

    prep_kernel<<<128, 256>>>(in_w, in_b, out_w, A_log);

    {
        size_t total = (size_t)MTOT * DM;
        int threads = 256;
        int blocks = (int)((total + threads - 1) / threads);
        conv_kernel<<<blocks, threads>>>(x, conv_w, conv_b);
    }

    {
        dim3 grid(MTOT / 128, NPROJ / 64);
        gemm1_kernel<<<grid, 256, G1_SMEM>>>();
    }

    elem_kernel<<<MTOT / 32, 256>>>();

    scan_kernel<<<(BATCH * DS * 32) / 128, 128>>>();

    {
        dim3 grid(MTOT / 128, DM / 128);
        gemm2_kernel<<<grid, 256, G2_SMEM>>>(out_b, out);
    }
}

// round 5
// speedup vs baseline: 2.3430x; 1.5885x over previous
#include <cuda_runtime.h>
#include <cuda_fp16.h>
#include <math.h>
#include <stdint.h>

// ---------------------------------------------------------------------------
// SelectiveSSM, HMMA fp16:
//  gemm1: single-product fp16 (error ~2^-11, calibrated ~3.5e-4 end-to-end)
//  gemm2: 3-product fp16 hi/lo split (error negligible)
// ---------------------------------------------------------------------------

#define DM    1024
#define DS    64
#define LSEQ  4096
#define BATCH 8
#define NPROJ 192
#define MTOT  (BATCH*LSEQ)
#define EPS_SSM 1e-4f

// ------------------------------- scratch -----------------------------------
__device__ __half g_xch [(size_t)MTOT*DM];      // conv out, fp16
__device__ __half g_W1h [NPROJ*DM];             // W1eff fp16
__device__ __half g_W2h [DM*DS];                // W2 hi fp16
__device__ __half g_W2l [DM*DS];                // W2 lo fp16
__device__ float  g_proj[(size_t)MTOT*NPROJ];
__device__ float  g_beff[NPROJ];
__device__ float  g_negA[DS];
__device__ float  g_Abar[(size_t)BATCH*DS*LSEQ];
__device__ float  g_Bbar[(size_t)BATCH*DS*LSEQ];
__device__ float  g_Cv  [(size_t)BATCH*DS*LSEQ];
__device__ float  g_y   [(size_t)BATCH*DS*LSEQ];
__device__ __half g_yth [(size_t)MTOT*DS];      // y transposed [m][s] hi
__device__ __half g_ytl [(size_t)MTOT*DS];      // y transposed [m][s] lo

// ------------------------------ helpers ------------------------------------
__device__ __forceinline__ uint32_t smem_u32(const void* p) {
    uint32_t a;
    asm("{ .reg .u64 t; cvta.to.shared.u64 t, %1; cvt.u32.u64 %0, t; }"
        : "=r"(a) : "l"(p));
    return a;
}
__device__ __forceinline__ void cp16(uint32_t dst, const void* src) {
    asm volatile("cp.async.ca.shared.global [%0], [%1], 16;"
                 :: "r"(dst), "l"(src));
}
#define CP_COMMIT()  asm volatile("cp.async.commit_group;" ::: "memory")
#define CP_WAIT0()   asm volatile("cp.async.wait_group 0;" ::: "memory")
#define CP_WAIT1()   asm volatile("cp.async.wait_group 1;" ::: "memory")

__device__ __forceinline__ void mma_f16(float& c0, float& c1, float& c2, float& c3,
                                        uint32_t a0, uint32_t a1, uint32_t a2, uint32_t a3,
                                        uint32_t b0, uint32_t b1) {
    asm volatile("mma.sync.aligned.m16n8k16.row.col.f32.f16.f16.f32 "
                 "{%0,%1,%2,%3}, {%4,%5,%6,%7}, {%8,%9}, {%0,%1,%2,%3};"
                 : "+f"(c0), "+f"(c1), "+f"(c2), "+f"(c3)
                 : "r"(a0), "r"(a1), "r"(a2), "r"(a3), "r"(b0), "r"(b1));
}

__device__ __forceinline__ void split_h(float x, __half& hi, __half& lo) {
    hi = __float2half_rn(x);
    lo = __float2half_rn(x - __half2float(hi));
}

// ---------------------------------------------------------------------------
// prep
// ---------------------------------------------------------------------------
__global__ void prep_kernel(const float* __restrict__ in_w,
                            const float* __restrict__ in_b,
                            const float* __restrict__ out_w,
                            const float* __restrict__ A_log)
{
    int stride = gridDim.x * blockDim.x;
    int tid = blockIdx.x * blockDim.x + threadIdx.x;

    for (int i = tid; i < NPROJ * DM; i += stride) {
        int n = i / DM, k = i % DM;
        float v;
        if (n < 64) {
            v = in_w[(size_t)n * DM + k];
        } else if (n < 128) {
            int s = n - 64;
            v = 0.5f * (in_w[(size_t)(64 + 2*s) * DM + k] +
                        in_w[(size_t)(64 + 2*s + 1) * DM + k]);
        } else {
            int s = n - 128;
            v = 0.5f * (in_w[(size_t)(192 + 2*s) * DM + k] +
                        in_w[(size_t)(192 + 2*s + 1) * DM + k]);
        }
        g_W1h[i] = __float2half_rn(v);
    }
    for (int i = tid; i < DM * DS; i += stride) {
        __half hi, lo; split_h(out_w[i], hi, lo);
        g_W2h[i] = hi; g_W2l[i] = lo;
    }
    for (int n = tid; n < NPROJ; n += stride) {
        float v;
        if (n < 64) v = in_b[n];
        else if (n < 128) { int s = n - 64;  v = 0.5f * (in_b[64 + 2*s]  + in_b[64 + 2*s + 1]); }
        else              { int s = n - 128; v = 0.5f * (in_b[192 + 2*s] + in_b[192 + 2*s + 1]); }
        g_beff[n] = v;
    }
    for (int s = tid; s < DS; s += stride) g_negA[s] = -expf(A_log[s]);
}

// ---------------------------------------------------------------------------
// conv -> fp16
// ---------------------------------------------------------------------------
__global__ void conv_kernel(const float* __restrict__ x,
                            const float* __restrict__ conv_w,
                            const float* __restrict__ conv_b)
{
    size_t idx = (size_t)blockIdx.x * blockDim.x + threadIdx.x;
    if (idx >= (size_t)MTOT * DM) return;
    int d = (int)(idx % DM);
    size_t bt = idx / DM;
    int t = (int)(bt % LSEQ);
    size_t b = bt / LSEQ;
    float r;
    if (t == LSEQ - 1) {
        r = 0.0f;
    } else {
        const float* xb = x + b * (size_t)LSEQ * DM;
        float w0 = conv_w[d*4+0], w1 = conv_w[d*4+1], w2 = conv_w[d*4+2], w3 = conv_w[d*4+3];
        r = conv_b[d];
        if (t - 1 >= 0)   r += w0 * xb[(size_t)(t-1) * DM + d];
        r += w1 * xb[(size_t)t * DM + d];
        r += w2 * xb[(size_t)(t+1) * DM + d];
        if (t + 2 < LSEQ) r += w3 * xb[(size_t)(t+2) * DM + d];
    }
    g_xch[idx] = __float2half_rn(r);
}

// ---------------------------------------------------------------------------
// GEMM1: proj[32768,192] = xc @ W1^T + beff    (fp16 single product)
// BM=128, BN=192 (full N), BK=32, 256 thr (8 warps 2m x 4n), warp 64x48
// smem rows: 32 fp16 = 64B + 16 pad = 80B stride; double buffered
// ---------------------------------------------------------------------------
#define G1_ROWB   80
#define G1_A_SZ   (128 * G1_ROWB)          // 10240
#define G1_B_SZ   (192 * G1_ROWB)          // 15360
#define G1_STAGE  (G1_A_SZ + G1_B_SZ)      // 25600
#define G1_SMEM   (2 * G1_STAGE)           // 51200

__global__ __launch_bounds__(256, 1) void gemm1_kernel()
{
    extern __shared__ char smem[];
    const uint32_t sb = smem_u32(smem);
    const int tid  = threadIdx.x;
    const int wid  = tid >> 5, lane = tid & 31;
    const int wm   = wid & 1;
    const int wn   = wid >> 1;
    const int m0   = blockIdx.x * 128;
    const int lr   = lane >> 2;
    const int lc   = lane & 3;

    float acc[4][6][4];
#pragma unroll
    for (int i = 0; i < 4; i++)
#pragma unroll
        for (int j = 0; j < 6; j++)
#pragma unroll
            for (int e = 0; e < 4; e++) acc[i][j][e] = 0.0f;

    auto load_stage = [&](int k0, int stage) {
        uint32_t Abase = sb + stage * G1_STAGE;
        uint32_t Bbase = Abase + G1_A_SZ;
#pragma unroll
        for (int i = 0; i < 2; ++i) {       // A: 512 x 16B
            int idx = tid + i * 256;
            int row = idx >> 2, cq = idx & 3;
            cp16(Abase + row * G1_ROWB + cq * 16,
                 &g_xch[(size_t)(m0 + row) * DM + k0 + cq * 8]);
        }
#pragma unroll
        for (int i = 0; i < 3; ++i) {       // B: 768 x 16B
            int idx = tid + i * 256;
            int row = idx >> 2, cq = idx & 3;
            cp16(Bbase + row * G1_ROWB + cq * 16,
                 &g_W1h[(size_t)row * DM + k0 + cq * 8]);
        }
    };

    load_stage(0, 0);
    CP_COMMIT();

    const int NCH = DM / 32;   // 32
    for (int c = 0; c < NCH; ++c) {
        if (c + 1 < NCH) { load_stage((c + 1) * 32, (c + 1) & 1); CP_COMMIT(); CP_WAIT1(); }
        else             { CP_WAIT0(); }
        __syncthreads();

        const char* Abase = smem + (c & 1) * G1_STAGE;
        const char* Bbase = Abase + G1_A_SZ;

#pragma unroll
        for (int ks = 0; ks < 2; ++ks) {
            const int kb = ks * 32 + lc * 4;
            uint32_t af[4][4];
#pragma unroll
            for (int mf = 0; mf < 4; ++mf) {
                int r0 = wm * 64 + mf * 16 + lr;
                const char* p0 = Abase + r0 * G1_ROWB + kb;
                const char* p1 = Abase + (r0 + 8) * G1_ROWB + kb;
                af[mf][0] = *(const uint32_t*)(p0);
                af[mf][1] = *(const uint32_t*)(p1);
                af[mf][2] = *(const uint32_t*)(p0 + 16);
                af[mf][3] = *(const uint32_t*)(p1 + 16);
            }
            uint32_t bf[6][2];
#pragma unroll
            for (int nf = 0; nf < 6; ++nf) {
                int n = wn * 48 + nf * 8 + lr;
                const char* p = Bbase + n * G1_ROWB + kb;
                bf[nf][0] = *(const uint32_t*)(p);
                bf[nf][1] = *(const uint32_t*)(p + 16);
            }
#pragma unroll
            for (int mf = 0; mf < 4; ++mf)
#pragma unroll
                for (int nf = 0; nf < 6; ++nf)
                    mma_f16(acc[mf][nf][0], acc[mf][nf][1], acc[mf][nf][2], acc[mf][nf][3],
                            af[mf][0], af[mf][1], af[mf][2], af[mf][3],
                            bf[nf][0], bf[nf][1]);
        }
        __syncthreads();
    }

#pragma unroll
    for (int mf = 0; mf < 4; ++mf) {
        int row = m0 + wm * 64 + mf * 16 + lr;
#pragma unroll
        for (int nf = 0; nf < 6; ++nf) {
            int col = wn * 48 + nf * 8 + lc * 2;
            float b0 = __ldg(&g_beff[col]), b1 = __ldg(&g_beff[col + 1]);
            float2 v0 = make_float2(acc[mf][nf][0] + b0, acc[mf][nf][1] + b1);
            float2 v1 = make_float2(acc[mf][nf][2] + b0, acc[mf][nf][3] + b1);
            *(float2*)&g_proj[(size_t)row * NPROJ + col]       = v0;
            *(float2*)&g_proj[(size_t)(row + 8) * NPROJ + col] = v1;
        }
    }
}

// ---------------------------------------------------------------------------
// elem: proj -> Abar/Bbar/C in [b][s][t]
// ---------------------------------------------------------------------------
__global__ __launch_bounds__(256) void elem_kernel()
{
    __shared__ float sp[32][NPROJ + 1];
    __shared__ float sA[DS];
    const int tid = threadIdx.x;
    const int m0 = blockIdx.x * 32;

    for (int i = tid; i < 32 * NPROJ; i += 256)
        sp[i / NPROJ][i % NPROJ] = g_proj[(size_t)m0 * NPROJ + i];
    if (tid < DS) sA[tid] = g_negA[tid];
    __syncthreads();

    const int t  = tid & 31;
    const int sr = tid >> 5;
    const int bidx  = m0 / LSEQ;
    const int tbase = m0 % LSEQ;

#pragma unroll
    for (int i = 0; i < 8; ++i) {
        int s = sr * 8 + i;
        float draw = sp[t][s];
        float bin  = sp[t][64 + s];
        float cc   = sp[t][128 + s];
        float A    = sA[s];
        float delta = (draw > 20.0f) ? draw : log1pf(expf(draw));
        float dA   = delta * A;
        float abar = expf(dA);
        float scale;
        if (fabsf(A) < EPS_SSM)
            scale = 1.0f + dA * 0.5f + dA * dA * (1.0f / 6.0f);
        else
            scale = (abar - 1.0f) / A;
        size_t o = ((size_t)(bidx * DS + s) << 12) + tbase + t;
        g_Abar[o] = abar;
        g_Bbar[o] = scale * bin;
        g_Cv[o]   = cc;
    }
}

// ---------------------------------------------------------------------------
// scan
// ---------------------------------------------------------------------------
__global__ __launch_bounds__(128) void scan_kernel()
{
    const int warp = (blockIdx.x * blockDim.x + threadIdx.x) >> 5;
    const int lane = threadIdx.x & 31;
    if (warp >= BATCH * DS) return;
    const size_t base = (size_t)warp * LSEQ;
    const float* ap = g_Abar + base;
    const float* bp = g_Bbar + base;
    const float* cp = g_Cv   + base;
    float*       yp = g_y    + base;

    float carry = 0.0f;
    for (int t0 = 0; t0 < LSEQ; t0 += 32) {
        float a = ap[t0 + lane];
        float b = bp[t0 + lane];
#pragma unroll
        for (int off = 1; off < 32; off <<= 1) {
            float apv = __shfl_up_sync(0xffffffffu, a, off);
            float bpv = __shfl_up_sync(0xffffffffu, b, off);
            if (lane >= off) { b = fmaf(a, bpv, b); a *= apv; }
        }
        float h = fmaf(a, carry, b);
        yp[t0 + lane] = cp[t0 + lane] * h;
        carry = __shfl_sync(0xffffffffu, h, 31);
    }
}

// ---------------------------------------------------------------------------
// ytr: y[b][s][t] fp32 -> g_yth/g_ytl [m=(b,t)][s] fp16 hi/lo
// block: one (b, t-tile of 64); smem [64 s][65] floats
// ---------------------------------------------------------------------------
__global__ __launch_bounds__(256) void ytr_kernel()
{
    __shared__ float sm[64][65];
    const int tid = threadIdx.x;
    const int b  = blockIdx.x >> 6;
    const int t0 = (blockIdx.x & 63) * 64;
    const float* yb = g_y + ((size_t)b * DS << 12);

    for (int idx = tid; idx < 64 * 64; idx += 256) {
        int s = idx >> 6, t = idx & 63;
        sm[s][t] = yb[((size_t)s << 12) + t0 + t];
    }
    __syncthreads();

    for (int idx = tid; idx < 64 * 32; idx += 256) {
        int t = idx >> 5, j = idx & 31;
        int s = j * 2;
        float v0 = sm[s][t], v1 = sm[s + 1][t];
        __half h0, l0, h1, l1;
        split_h(v0, h0, l0);
        split_h(v1, h1, l1);
        size_t m = ((size_t)b << 12) + t0 + t;
        *(__half2*)&g_yth[m * DS + s] = __halves2half2(h0, h1);
        *(__half2*)&g_ytl[m * DS + s] = __halves2half2(l0, l1);
    }
}

// ---------------------------------------------------------------------------
// GEMM2: out[m][n] = yt[m][s] @ W2[n][s]^T + out_b   (fp16 3-product)
// BM=128, BN=128, K=64 single stage; warp tile 64x32; row stride 144B
// ---------------------------------------------------------------------------
#define G2_ROWB  144
#define G2_T_SZ  (128 * G2_ROWB)   // 18432
#define G2_SMEM  (4 * G2_T_SZ)     // 73728

__global__ __launch_bounds__(256, 2) void gemm2_kernel(const float* __restrict__ out_b,
                                                       float* __restrict__ out)
{
    extern __shared__ char smem[];
    const uint32_t sb = smem_u32(smem);
    const int tid = threadIdx.x;
    const int wid = tid >> 5, lane = tid & 31;
    const int wm  = wid & 1;
    const int wn  = wid >> 1;
    const int m0  = blockIdx.x * 128;
    const int n0  = blockIdx.y * 128;
    const int lr  = lane >> 2;
    const int lc  = lane & 3;

    const char* Ahi = smem;
    const char* Alo = smem + G2_T_SZ;
    const char* Bhi = smem + 2*G2_T_SZ;
    const char* Blo = smem + 3*G2_T_SZ;

    // A: yt rows of 128B (8 chunks); B: W2 rows of 128B
#pragma unroll
    for (int i = 0; i < 4; ++i) {
        int idx = tid + i * 256;
        int row = idx >> 3, cq = idx & 7;
        uint32_t d = row * G2_ROWB + cq * 16;
        cp16(sb + d,            &g_yth[(size_t)(m0 + row) * DS + cq * 8]);
        cp16(sb + G2_T_SZ + d,  &g_ytl[(size_t)(m0 + row) * DS + cq * 8]);
        cp16(sb + 2*G2_T_SZ + d, &g_W2h[(size_t)(n0 + row) * DS + cq * 8]);
        cp16(sb + 3*G2_T_SZ + d, &g_W2l[(size_t)(n0 + row) * DS + cq * 8]);
    }
    CP_COMMIT();
    CP_WAIT0();
    __syncthreads();

    float acc[4][4][4];
#pragma unroll
    for (int i = 0; i < 4; i++)
#pragma unroll
        for (int j = 0; j < 4; j++)
#pragma unroll
            for (int e = 0; e < 4; e++) acc[i][j][e] = 0.0f;

#pragma unroll
    for (int ks = 0; ks < 4; ++ks) {
        const int kb = ks * 32 + lc * 4;
        uint32_t ah[4][4], al[4][4];
#pragma unroll
        for (int mf = 0; mf < 4; ++mf) {
            int r0 = wm * 64 + mf * 16 + lr;
            const char* p0 = Ahi + r0 * G2_ROWB + kb;
            const char* p1 = Ahi + (r0 + 8) * G2_ROWB + kb;
            ah[mf][0] = *(const uint32_t*)(p0);
            ah[mf][1] = *(const uint32_t*)(p1);
            ah[mf][2] = *(const uint32_t*)(p0 + 16);
            ah[mf][3] = *(const uint32_t*)(p1 + 16);
            const char* q0 = Alo + r0 * G2_ROWB + kb;
            const char* q1 = Alo + (r0 + 8) * G2_ROWB + kb;
            al[mf][0] = *(const uint32_t*)(q0);
            al[mf][1] = *(const uint32_t*)(q1);
            al[mf][2] = *(const uint32_t*)(q0 + 16);
            al[mf][3] = *(const uint32_t*)(q1 + 16);
        }
        uint32_t bh[4][2], bl[4][2];
#pragma unroll
        for (int nf = 0; nf < 4; ++nf) {
            int n = wn * 32 + nf * 8 + lr;
            const char* p = Bhi + n * G2_ROWB + kb;
            bh[nf][0] = *(const uint32_t*)(p);
            bh[nf][1] = *(const uint32_t*)(p + 16);
            const char* q = Blo + n * G2_ROWB + kb;
            bl[nf][0] = *(const uint32_t*)(q);
            bl[nf][1] = *(const uint32_t*)(q + 16);
        }
#pragma unroll
        for (int mf = 0; mf < 4; ++mf)
#pragma unroll
            for (int nf = 0; nf < 4; ++nf) {
                float* cc = acc[mf][nf];
                mma_f16(cc[0], cc[1], cc[2], cc[3],
                        ah[mf][0], ah[mf][1], ah[mf][2], ah[mf][3],
                        bh[nf][0], bh[nf][1]);
                mma_f16(cc[0], cc[1], cc[2], cc[3],
                        ah[mf][0], ah[mf][1], ah[mf][2], ah[mf][3],
                        bl[nf][0], bl[nf][1]);
                mma_f16(cc[0], cc[1], cc[2], cc[3],
                        al[mf][0], al[mf][1], al[mf][2], al[mf][3],
                        bh[nf][0], bh[nf][1]);
            }
    }

#pragma unroll
    for (int mf = 0; mf < 4; ++mf) {
        int row = m0 + wm * 64 + mf * 16 + lr;
#pragma unroll
        for (int nf = 0; nf < 4; ++nf) {
            int col = n0 + wn * 32 + nf * 8 + lc * 2;
            float b0 = __ldg(&out_b[col]), b1 = __ldg(&out_b[col + 1]);
            float2 v0 = make_float2(acc[mf][nf][0] + b0, acc[mf][nf][1] + b1);
            float2 v1 = make_float2(acc[mf][nf][2] + b0, acc[mf][nf][3] + b1);
            *(float2*)&out[(size_t)row * DM + col]       = v0;
            *(float2*)&out[(size_t)(row + 8) * DM + col] = v1;
        }
    }
}

// ---------------------------------------------------------------------------
extern "C" void kernel_launch(void* const* d_in, const int* in_sizes, int n_in,
                              void* d_out, int out_size)
{
    const float* x      = (const float*)d_in[0];
    const float* conv_w = (const float*)d_in[1];
    const float* conv_b = (const float*)d_in[2];
    const float* in_w   = (const float*)d_in[3];
    const float* in_b   = (const float*)d_in[4];
    const float* A_log  = (const float*)d_in[5];
    const float* out_w  = (const float*)d_in[6];
    const float* out_b  = (const float*)d_in[7];
    float* out = (float*)d_out;

    cudaFuncSetAttribute(gemm1_kernel, cudaFuncAttributeMaxDynamicSharedMemorySize, G1_SMEM);
    cudaFuncSetAttribute(gemm2_kernel, cudaFuncAttributeMaxDynamicSharedMemorySize, G2_SMEM);

    prep_kernel<<<128, 256>>>(in_w, in_b, out_w, A_log);

    {
        size_t total = (size_t)MTOT * DM;
        int threads = 256;
        int blocks = (int)((total + threads - 1) / threads);
        conv_kernel<<<blocks, threads>>>(x, conv_w, conv_b);
    }

    gemm1_kernel<<<MTOT / 128, 256, G1_SMEM>>>();

    elem_kernel<<<MTOT / 32, 256>>>();

    scan_kernel<<<(BATCH * DS * 32) / 128, 128>>>();

    ytr_kernel<<<BATCH * (LSEQ / 64), 256>>>();

    {
        dim3 grid(MTOT / 128, DM / 128);
        gemm2_kernel<<<grid, 256, G2_SMEM>>>(out_b, out);
    }
}

// round 7
// speedup vs baseline: 3.7911x; 1.6181x over previous
#include <cuda_runtime.h>
#include <cuda_fp16.h>
#include <math.h>
#include <stdint.h>

// ---------------------------------------------------------------------------
// SelectiveSSM, HMMA fp16:
//  gemm1: single-product fp16 ;  gemm2: 3-product fp16 hi/lo split
//  R6: coarsened conv, block-parallel scan, gemm2 grid swapped for L2 reuse
// ---------------------------------------------------------------------------

#define DM    1024
#define DS    64
#define LSEQ  4096
#define BATCH 8
#define NPROJ 192
#define MTOT  (BATCH*LSEQ)
#define EPS_SSM 1e-4f

// ------------------------------- scratch -----------------------------------
__device__ __half g_xch [(size_t)MTOT*DM];      // conv out, fp16
__device__ __half g_W1h [NPROJ*DM];             // W1eff fp16
__device__ __half g_W2h [DM*DS];                // W2 hi fp16
__device__ __half g_W2l [DM*DS];                // W2 lo fp16
__device__ float  g_proj[(size_t)MTOT*NPROJ];
__device__ float  g_beff[NPROJ];
__device__ float  g_negA[DS];
__device__ float  g_Abar[(size_t)BATCH*DS*LSEQ];
__device__ float  g_Bbar[(size_t)BATCH*DS*LSEQ];
__device__ float  g_Cv  [(size_t)BATCH*DS*LSEQ];
__device__ float  g_y   [(size_t)BATCH*DS*LSEQ];
__device__ __half g_yth [(size_t)MTOT*DS];      // y transposed [m][s] hi
__device__ __half g_ytl [(size_t)MTOT*DS];      // y transposed [m][s] lo

// ------------------------------ helpers ------------------------------------
__device__ __forceinline__ uint32_t smem_u32(const void* p) {
    uint32_t a;
    asm("{ .reg .u64 t; cvta.to.shared.u64 t, %1; cvt.u32.u64 %0, t; }"
        : "=r"(a) : "l"(p));
    return a;
}
__device__ __forceinline__ void cp16(uint32_t dst, const void* src) {
    asm volatile("cp.async.ca.shared.global [%0], [%1], 16;"
                 :: "r"(dst), "l"(src));
}
#define CP_COMMIT()  asm volatile("cp.async.commit_group;" ::: "memory")
#define CP_WAIT0()   asm volatile("cp.async.wait_group 0;" ::: "memory")
#define CP_WAIT1()   asm volatile("cp.async.wait_group 1;" ::: "memory")

__device__ __forceinline__ void mma_f16(float& c0, float& c1, float& c2, float& c3,
                                        uint32_t a0, uint32_t a1, uint32_t a2, uint32_t a3,
                                        uint32_t b0, uint32_t b1) {
    asm volatile("mma.sync.aligned.m16n8k16.row.col.f32.f16.f16.f32 "
                 "{%0,%1,%2,%3}, {%4,%5,%6,%7}, {%8,%9}, {%0,%1,%2,%3};"
                 : "+f"(c0), "+f"(c1), "+f"(c2), "+f"(c3)
                 : "r"(a0), "r"(a1), "r"(a2), "r"(a3), "r"(b0), "r"(b1));
}

__device__ __forceinline__ void split_h(float x, __half& hi, __half& lo) {
    hi = __float2half_rn(x);
    lo = __float2half_rn(x - __half2float(hi));
}

// ---------------------------------------------------------------------------
// prep
// ---------------------------------------------------------------------------
__global__ void prep_kernel(const float* __restrict__ in_w,
                            const float* __restrict__ in_b,
                            const float* __restrict__ out_w,
                            const float* __restrict__ A_log)
{
    int stride = gridDim.x * blockDim.x;
    int tid = blockIdx.x * blockDim.x + threadIdx.x;

    for (int i = tid; i < NPROJ * DM; i += stride) {
        int n = i / DM, k = i % DM;
        float v;
        if (n < 64) {
            v = in_w[(size_t)n * DM + k];
        } else if (n < 128) {
            int s = n - 64;
            v = 0.5f * (in_w[(size_t)(64 + 2*s) * DM + k] +
                        in_w[(size_t)(64 + 2*s + 1) * DM + k]);
        } else {
            int s = n - 128;
            v = 0.5f * (in_w[(size_t)(192 + 2*s) * DM + k] +
                        in_w[(size_t)(192 + 2*s + 1) * DM + k]);
        }
        g_W1h[i] = __float2half_rn(v);
    }
    for (int i = tid; i < DM * DS; i += stride) {
        __half hi, lo; split_h(out_w[i], hi, lo);
        g_W2h[i] = hi; g_W2l[i] = lo;
    }
    for (int n = tid; n < NPROJ; n += stride) {
        float v;
        if (n < 64) v = in_b[n];
        else if (n < 128) { int s = n - 64;  v = 0.5f * (in_b[64 + 2*s]  + in_b[64 + 2*s + 1]); }
        else              { int s = n - 128; v = 0.5f * (in_b[192 + 2*s] + in_b[192 + 2*s + 1]); }
        g_beff[n] = v;
    }
    for (int s = tid; s < DS; s += stride) g_negA[s] = -expf(A_log[s]);
}

// ---------------------------------------------------------------------------
// conv: 4-way t coarsened, one channel d per thread; 7 loads -> 4 outputs
// ---------------------------------------------------------------------------
__global__ void conv_kernel(const float* __restrict__ x,
                            const float* __restrict__ conv_w,
                            const float* __restrict__ conv_b)
{
    size_t idx = (size_t)blockIdx.x * blockDim.x + threadIdx.x;
    if (idx >= (size_t)(MTOT / 4) * DM) return;
    const int d  = (int)(idx % DM);
    const size_t m4 = idx / DM;
    const int b  = (int)(m4 >> 10);             // 1024 groups of 4 per batch
    const int tg = (int)(m4 & 1023) * 4;        // first t of this group

    const float* xb = x + ((size_t)b << 12) * DM;
    const float w0 = __ldg(&conv_w[d*4+0]);
    const float w1 = __ldg(&conv_w[d*4+1]);
    const float w2 = __ldg(&conv_w[d*4+2]);
    const float w3 = __ldg(&conv_w[d*4+3]);
    const float bias = __ldg(&conv_b[d]);

    const float xm1 = (tg > 0) ? xb[(size_t)(tg-1) * DM + d] : 0.0f;   // w0 term drops at t==0
    const float x0 = xb[(size_t)(tg+0) * DM + d];
    const float x1 = xb[(size_t)(tg+1) * DM + d];
    const float x2 = xb[(size_t)(tg+2) * DM + d];
    const float x3 = xb[(size_t)(tg+3) * DM + d];
    const float x4 = (tg + 4 < LSEQ) ? xb[(size_t)(tg+4) * DM + d] : 0.0f;
    const float x5 = (tg + 5 < LSEQ) ? xb[(size_t)(tg+5) * DM + d] : 0.0f;

    float r0 = bias + w0*xm1 + w1*x0 + w2*x1 + w3*x2;
    float r1 = bias + w0*x0  + w1*x1 + w2*x2 + w3*x3;
    float r2 = bias + w0*x1  + w1*x2 + w2*x3 + w3*x4;
    float r3 = (tg + 3 == LSEQ - 1) ? 0.0f
             : bias + w0*x2  + w1*x3 + w2*x4 + w3*x5;

    const size_t o = (((size_t)b << 12) + tg) * DM + d;
    g_xch[o]          = __float2half_rn(r0);
    g_xch[o + DM]     = __float2half_rn(r1);
    g_xch[o + 2*DM]   = __float2half_rn(r2);
    g_xch[o + 3*DM]   = __float2half_rn(r3);
}

// ---------------------------------------------------------------------------
// GEMM1: proj[32768,192] = xc @ W1^T + beff    (fp16 single product)
// BM=128, BN=192, BK=32, 256 thr (8 warps 2m x 4n), warp 64x48
// ---------------------------------------------------------------------------
#define G1_ROWB   80
#define G1_A_SZ   (128 * G1_ROWB)
#define G1_B_SZ   (192 * G1_ROWB)
#define G1_STAGE  (G1_A_SZ + G1_B_SZ)
#define G1_SMEM   (2 * G1_STAGE)

__global__ __launch_bounds__(256, 1) void gemm1_kernel()
{
    extern __shared__ char smem[];
    const uint32_t sb = smem_u32(smem);
    const int tid  = threadIdx.x;
    const int wid  = tid >> 5, lane = tid & 31;
    const int wm   = wid & 1;
    const int wn   = wid >> 1;
    const int m0   = blockIdx.x * 128;
    const int lr   = lane >> 2;
    const int lc   = lane & 3;

    float acc[4][6][4];
#pragma unroll
    for (int i = 0; i < 4; i++)
#pragma unroll
        for (int j = 0; j < 6; j++)
#pragma unroll
            for (int e = 0; e < 4; e++) acc[i][j][e] = 0.0f;

    auto load_stage = [&](int k0, int stage) {
        uint32_t Abase = sb + stage * G1_STAGE;
        uint32_t Bbase = Abase + G1_A_SZ;
#pragma unroll
        for (int i = 0; i < 2; ++i) {
            int idx = tid + i * 256;
            int row = idx >> 2, cq = idx & 3;
            cp16(Abase + row * G1_ROWB + cq * 16,
                 &g_xch[(size_t)(m0 + row) * DM + k0 + cq * 8]);
        }
#pragma unroll
        for (int i = 0; i < 3; ++i) {
            int idx = tid + i * 256;
            int row = idx >> 2, cq = idx & 3;
            cp16(Bbase + row * G1_ROWB + cq * 16,
                 &g_W1h[(size_t)row * DM + k0 + cq * 8]);
        }
    };

    load_stage(0, 0);
    CP_COMMIT();

    const int NCH = DM / 32;
    for (int c = 0; c < NCH; ++c) {
        if (c + 1 < NCH) { load_stage((c + 1) * 32, (c + 1) & 1); CP_COMMIT(); CP_WAIT1(); }
        else             { CP_WAIT0(); }
        __syncthreads();

        const char* Abase = smem + (c & 1) * G1_STAGE;
        const char* Bbase = Abase + G1_A_SZ;

#pragma unroll
        for (int ks = 0; ks < 2; ++ks) {
            const int kb = ks * 32 + lc * 4;
            uint32_t af[4][4];
#pragma unroll
            for (int mf = 0; mf < 4; ++mf) {
                int r0 = wm * 64 + mf * 16 + lr;
                const char* p0 = Abase + r0 * G1_ROWB + kb;
                const char* p1 = Abase + (r0 + 8) * G1_ROWB + kb;
                af[mf][0] = *(const uint32_t*)(p0);
                af[mf][1] = *(const uint32_t*)(p1);
                af[mf][2] = *(const uint32_t*)(p0 + 16);
                af[mf][3] = *(const uint32_t*)(p1 + 16);
            }
            uint32_t bf[6][2];
#pragma unroll
            for (int nf = 0; nf < 6; ++nf) {
                int n = wn * 48 + nf * 8 + lr;
                const char* p = Bbase + n * G1_ROWB + kb;
                bf[nf][0] = *(const uint32_t*)(p);
                bf[nf][1] = *(const uint32_t*)(p + 16);
            }
#pragma unroll
            for (int mf = 0; mf < 4; ++mf)
#pragma unroll
                for (int nf = 0; nf < 6; ++nf)
                    mma_f16(acc[mf][nf][0], acc[mf][nf][1], acc[mf][nf][2], acc[mf][nf][3],
                            af[mf][0], af[mf][1], af[mf][2], af[mf][3],
                            bf[nf][0], bf[nf][1]);
        }
        __syncthreads();
    }

#pragma unroll
    for (int mf = 0; mf < 4; ++mf) {
        int row = m0 + wm * 64 + mf * 16 + lr;
#pragma unroll
        for (int nf = 0; nf < 6; ++nf) {
            int col = wn * 48 + nf * 8 + lc * 2;
            float b0 = __ldg(&g_beff[col]), b1 = __ldg(&g_beff[col + 1]);
            float2 v0 = make_float2(acc[mf][nf][0] + b0, acc[mf][nf][1] + b1);
            float2 v1 = make_float2(acc[mf][nf][2] + b0, acc[mf][nf][3] + b1);
            *(float2*)&g_proj[(size_t)row * NPROJ + col]       = v0;
            *(float2*)&g_proj[(size_t)(row + 8) * NPROJ + col] = v1;
        }
    }
}

// ---------------------------------------------------------------------------
// elem: proj -> Abar/Bbar/C in [b][s][t]
// ---------------------------------------------------------------------------
__global__ __launch_bounds__(256) void elem_kernel()
{
    __shared__ float sp[32][NPROJ + 1];
    __shared__ float sA[DS];
    const int tid = threadIdx.x;
    const int m0 = blockIdx.x * 32;

    for (int i = tid; i < 32 * NPROJ; i += 256)
        sp[i / NPROJ][i % NPROJ] = g_proj[(size_t)m0 * NPROJ + i];
    if (tid < DS) sA[tid] = g_negA[tid];
    __syncthreads();

    const int t  = tid & 31;
    const int sr = tid >> 5;
    const int bidx  = m0 / LSEQ;
    const int tbase = m0 % LSEQ;

#pragma unroll
    for (int i = 0; i < 8; ++i) {
        int s = sr * 8 + i;
        float draw = sp[t][s];
        float bin  = sp[t][64 + s];
        float cc   = sp[t][128 + s];
        float A    = sA[s];
        float delta = (draw > 20.0f) ? draw : log1pf(expf(draw));
        float dA   = delta * A;
        float abar = expf(dA);
        float scale;
        if (fabsf(A) < EPS_SSM)
            scale = 1.0f + dA * 0.5f + dA * dA * (1.0f / 6.0f);
        else
            scale = (abar - 1.0f) / A;
        size_t o = ((size_t)(bidx * DS + s) << 12) + tbase + t;
        g_Abar[o] = abar;
        g_Bbar[o] = scale * bin;
        g_Cv[o]   = cc;
    }
}

// ---------------------------------------------------------------------------
// scan: one block (1024 thr) per (b,s); thread-coarsen 4 + warp scan +
// block scan of warp aggregates; y = C*h
// operator f(prev,cur): A=Ap*Ac, B=Bp*Ac+Bc
// ---------------------------------------------------------------------------
__global__ __launch_bounds__(1024) void scan_kernel()
{
    __shared__ float sA[32], sB[32];
    const size_t base = (size_t)blockIdx.x * LSEQ;
    const int tid = threadIdx.x;
    const int lane = tid & 31, warp = tid >> 5;

    const float4 av = *(const float4*)&g_Abar[base + tid * 4];
    const float4 bv = *(const float4*)&g_Bbar[base + tid * 4];

    // local composite of 4 elements
    float A = av.x, B = bv.x;
    B = fmaf(B, av.y, bv.y); A *= av.y;
    B = fmaf(B, av.z, bv.z); A *= av.z;
    B = fmaf(B, av.w, bv.w); A *= av.w;

    // warp inclusive scan of composites
    float Ai = A, Bi = B;
#pragma unroll
    for (int off = 1; off < 32; off <<= 1) {
        float ap = __shfl_up_sync(0xffffffffu, Ai, off);
        float bp = __shfl_up_sync(0xffffffffu, Bi, off);
        if (lane >= off) { Bi = fmaf(Ai, bp, Bi); Ai *= ap; }
    }
    // exclusive per-lane
    float Ae = __shfl_up_sync(0xffffffffu, Ai, 1);
    float Be = __shfl_up_sync(0xffffffffu, Bi, 1);
    if (lane == 0) { Ae = 1.0f; Be = 0.0f; }

    if (lane == 31) { sA[warp] = Ai; sB[warp] = Bi; }
    __syncthreads();

    if (warp == 0) {
        float a = sA[lane], b = sB[lane];
#pragma unroll
        for (int off = 1; off < 32; off <<= 1) {
            float ap = __shfl_up_sync(0xffffffffu, a, off);
            float bp = __shfl_up_sync(0xffffffffu, b, off);
            if (lane >= off) { b = fmaf(a, bp, b); a *= ap; }
        }
        float ax = __shfl_up_sync(0xffffffffu, a, 1);
        float bx = __shfl_up_sync(0xffffffffu, b, 1);
        if (lane == 0) { ax = 1.0f; bx = 0.0f; }
        sA[lane] = ax; sB[lane] = bx;
    }
    __syncthreads();

    // carry = f(warp_excl, lane_excl); h_in = B-part (h_{-1}=0)
    const float hin = fmaf(sB[warp], Ae, Be);

    const float4 cv = *(const float4*)&g_Cv[base + tid * 4];
    float h0 = fmaf(av.x, hin, bv.x);
    float h1 = fmaf(av.y, h0, bv.y);
    float h2 = fmaf(av.z, h1, bv.z);
    float h3 = fmaf(av.w, h2, bv.w);
    float4 yv = make_float4(cv.x * h0, cv.y * h1, cv.z * h2, cv.w * h3);
    *(float4*)&g_y[base + tid * 4] = yv;
}

// ---------------------------------------------------------------------------
// ytr: y[b][s][t] fp32 -> g_yth/g_ytl [m=(b,t)][s] fp16 hi/lo
// ---------------------------------------------------------------------------
__global__ __launch_bounds__(256) void ytr_kernel()
{
    __shared__ float sm[64][65];
    const int tid = threadIdx.x;
    const int b  = blockIdx.x >> 6;
    const int t0 = (blockIdx.x & 63) * 64;
    const float* yb = g_y + ((size_t)b * DS << 12);

    for (int idx = tid; idx < 64 * 64; idx += 256) {
        int s = idx >> 6, t = idx & 63;
        sm[s][t] = yb[((size_t)s << 12) + t0 + t];
    }
    __syncthreads();

    for (int idx = tid; idx < 64 * 32; idx += 256) {
        int t = idx >> 5, j = idx & 31;
        int s = j * 2;
        float v0 = sm[s][t], v1 = sm[s + 1][t];
        __half h0, l0, h1, l1;
        split_h(v0, h0, l0);
        split_h(v1, h1, l1);
        size_t m = ((size_t)b << 12) + t0 + t;
        *(__half2*)&g_yth[m * DS + s] = __halves2half2(h0, h1);
        *(__half2*)&g_ytl[m * DS + s] = __halves2half2(l0, l1);
    }
}

// ---------------------------------------------------------------------------
// GEMM2: out[m][n] = yt[m][s] @ W2[n][s]^T + out_b   (fp16 3-product)
// grid: (n-tiles, m-tiles) so consecutive CTAs share the A tile (L2 reuse)
// ---------------------------------------------------------------------------
#define G2_ROWB  144
#define G2_T_SZ  (128 * G2_ROWB)
#define G2_SMEM  (4 * G2_T_SZ)

__global__ __launch_bounds__(256, 2) void gemm2_kernel(const float* __restrict__ out_b,
                                                       float* __restrict__ out)
{
    extern __shared__ char smem[];
    const uint32_t sb = smem_u32(smem);
    const int tid = threadIdx.x;
    const int wid = tid >> 5, lane = tid & 31;
    const int wm  = wid & 1;
    const int wn  = wid >> 1;
    const int n0  = blockIdx.x * 128;
    const int m0  = blockIdx.y * 128;
    const int lr  = lane >> 2;
    const int lc  = lane & 3;

    const char* Ahi = smem;
    const char* Alo = smem + G2_T_SZ;
    const char* Bhi = smem + 2*G2_T_SZ;
    const char* Blo = smem + 3*G2_T_SZ;

#pragma unroll
    for (int i = 0; i < 4; ++i) {
        int idx = tid + i * 256;
        int row = idx >> 3, cq = idx & 7;
        uint32_t d = row * G2_ROWB + cq * 16;
        cp16(sb + d,             &g_yth[(size_t)(m0 + row) * DS + cq * 8]);
        cp16(sb + G2_T_SZ + d,   &g_ytl[(size_t)(m0 + row) * DS + cq * 8]);
        cp16(sb + 2*G2_T_SZ + d, &g_W2h[(size_t)(n0 + row) * DS + cq * 8]);
        cp16(sb + 3*G2_T_SZ + d, &g_W2l[(size_t)(n0 + row) * DS + cq * 8]);
    }
    CP_COMMIT();
    CP_WAIT0();
    __syncthreads();

    float acc[4][4][4];
#pragma unroll
    for (int i = 0; i < 4; i++)
#pragma unroll
        for (int j = 0; j < 4; j++)
#pragma unroll
            for (int e = 0; e < 4; e++) acc[i][j][e] = 0.0f;

#pragma unroll
    for (int ks = 0; ks < 4; ++ks) {
        const int kb = ks * 32 + lc * 4;
        uint32_t ah[4][4], al[4][4];
#pragma unroll
        for (int mf = 0; mf < 4; ++mf) {
            int r0 = wm * 64 + mf * 16 + lr;
            const char* p0 = Ahi + r0 * G2_ROWB + kb;
            const char* p1 = Ahi + (r0 + 8) * G2_ROWB + kb;
            ah[mf][0] = *(const uint32_t*)(p0);
            ah[mf][1] = *(const uint32_t*)(p1);
            ah[mf][2] = *(const uint32_t*)(p0 + 16);
            ah[mf][3] = *(const uint32_t*)(p1 + 16);
            const char* q0 = Alo + r0 * G2_ROWB + kb;
            const char* q1 = Alo + (r0 + 8) * G2_ROWB + kb;
            al[mf][0] = *(const uint32_t*)(q0);
            al[mf][1] = *(const uint32_t*)(q1);
            al[mf][2] = *(const uint32_t*)(q0 + 16);
            al[mf][3] = *(const uint32_t*)(q1 + 16);
        }
        uint32_t bh[4][2], bl[4][2];
#pragma unroll
        for (int nf = 0; nf < 4; ++nf) {
            int n = wn * 32 + nf * 8 + lr;
            const char* p = Bhi + n * G2_ROWB + kb;
            bh[nf][0] = *(const uint32_t*)(p);
            bh[nf][1] = *(const uint32_t*)(p + 16);
            const char* q = Blo + n * G2_ROWB + kb;
            bl[nf][0] = *(const uint32_t*)(q);
            bl[nf][1] = *(const uint32_t*)(q + 16);
        }
#pragma unroll
        for (int mf = 0; mf < 4; ++mf)
#pragma unroll
            for (int nf = 0; nf < 4; ++nf) {
                float* cc = acc[mf][nf];
                mma_f16(cc[0], cc[1], cc[2], cc[3],
                        ah[mf][0], ah[mf][1], ah[mf][2], ah[mf][3],
                        bh[nf][0], bh[nf][1]);
                mma_f16(cc[0], cc[1], cc[2], cc[3],
                        ah[mf][0], ah[mf][1], ah[mf][2], ah[mf][3],
                        bl[nf][0], bl[nf][1]);
                mma_f16(cc[0], cc[1], cc[2], cc[3],
                        al[mf][0], al[mf][1], al[mf][2], al[mf][3],
                        bh[nf][0], bh[nf][1]);
            }
    }

#pragma unroll
    for (int mf = 0; mf < 4; ++mf) {
        int row = m0 + wm * 64 + mf * 16 + lr;
#pragma unroll
        for (int nf = 0; nf < 4; ++nf) {
            int col = n0 + wn * 32 + nf * 8 + lc * 2;
            float b0 = __ldg(&out_b[col]), b1 = __ldg(&out_b[col + 1]);
            float2 v0 = make_float2(acc[mf][nf][0] + b0, acc[mf][nf][1] + b1);
            float2 v1 = make_float2(acc[mf][nf][2] + b0, acc[mf][nf][3] + b1);
            *(float2*)&out[(size_t)row * DM + col]       = v0;
            *(float2*)&out[(size_t)(row + 8) * DM + col] = v1;
        }
    }
}

// ---------------------------------------------------------------------------
extern "C" void kernel_launch(void* const* d_in, const int* in_sizes, int n_in,
                              void* d_out, int out_size)
{
    const float* x      = (const float*)d_in[0];
    const float* conv_w = (const float*)d_in[1];
    const float* conv_b = (const float*)d_in[2];
    const float* in_w   = (const float*)d_in[3];
    const float* in_b   = (const float*)d_in[4];
    const float* A_log  = (const float*)d_in[5];
    const float* out_w  = (const float*)d_in[6];
    const float* out_b  = (const float*)d_in[7];
    float* out = (float*)d_out;

    cudaFuncSetAttribute(gemm1_kernel, cudaFuncAttributeMaxDynamicSharedMemorySize, G1_SMEM);
    cudaFuncSetAttribute(gemm2_kernel, cudaFuncAttributeMaxDynamicSharedMemorySize, G2_SMEM);

    prep_kernel<<<128, 256>>>(in_w, in_b, out_w, A_log);

    {
        size_t total = (size_t)(MTOT / 4) * DM;    // 8.4M threads
        int threads = 256;
        int blocks = (int)((total + threads - 1) / threads);
        conv_kernel<<<blocks, threads>>>(x, conv_w, conv_b);
    }

    gemm1_kernel<<<MTOT / 128, 256, G1_SMEM>>>();

    elem_kernel<<<MTOT / 32, 256>>>();

    scan_kernel<<<BATCH * DS, 1024>>>();

    ytr_kernel<<<BATCH * (LSEQ / 64), 256>>>();

    {
        dim3 grid(DM / 128, MTOT / 128);
        gemm2_kernel<<<grid, 256, G2_SMEM>>>(out_b, out);
    }
}